// round 1
// baseline (speedup 1.0000x reference)
#include <cuda_runtime.h>
#include <cstdint>
#include <cstddef>

// Problem dims
#define TT 64
#define BB 512
#define DD 512
#define HH 2048

// ---------------- scratch (device globals; no allocation allowed) ----------
__device__ float g_ycur[BB * DD];             // current state y
__device__ float g_kbuf[BB * DD];             // most recent k_i
__device__ float g_acc[BB * DD];              // k1 + 2k2 + 2k3 (+ k4)
__device__ float g_h[(size_t)BB * HH];        // tanh hidden activations

// ---------------- helpers --------------------------------------------------
__device__ __forceinline__ uint32_t f2tf(float x) {
    uint32_t u;
    asm("cvt.rna.tf32.f32 %0, %1;" : "=r"(u) : "f"(x));
    return u;
}

__device__ __forceinline__ void mma_tf32(float c[4],
                                         uint32_t a0, uint32_t a1, uint32_t a2, uint32_t a3,
                                         uint32_t b0, uint32_t b1) {
    asm volatile(
        "mma.sync.aligned.m16n8k8.row.col.f32.tf32.tf32.f32 "
        "{%0,%1,%2,%3},{%4,%5,%6,%7},{%8,%9},{%0,%1,%2,%3};"
        : "+f"(c[0]), "+f"(c[1]), "+f"(c[2]), "+f"(c[3])
        : "r"(a0), "r"(a1), "r"(a2), "r"(a3), "r"(b0), "r"(b1));
}

// ---------------- init: out[0] = y0, g_ycur = y0 ---------------------------
__global__ void init_kernel(const float* __restrict__ y0, float* __restrict__ out) {
    int idx = blockIdx.x * blockDim.x + threadIdx.x;  // float4 index
    float4 v = ((const float4*)y0)[idx];
    ((float4*)out)[idx] = v;
    ((float4*)g_ycur)[idx] = v;
}

// ============================================================================
// GEMM1: g_h = tanh( (g_ycur + cf * g_kbuf) [M=BB x K=DD] @ W1 [DD x HH] + b1 )
// CTA tile 64x128, BK=16, 256 threads, warps 2x4, warp tile 32x32.
// ============================================================================
#define BM1 64
#define BN1 128
#define BKK 16
#define LDA 20    // BKK + 4  (mult of 4 -> float4-aligned rows; conflict-free a-frags)
#define LDB1 136  // BN1 + 8  (136 % 32 == 8 -> conflict-free b-frags)

__global__ __launch_bounds__(256) void gemm1_kernel(const float* __restrict__ W1,
                                                    const float* __restrict__ b1,
                                                    float cf) {
    __shared__ uint32_t sA[2][BM1 * LDA];
    __shared__ uint32_t sB[2][BKK * LDB1];

    const int tid = threadIdx.x;
    const int lane = tid & 31, warp = tid >> 5;
    const int g = lane >> 2, tg = lane & 3;
    const int wm = (warp >> 2) * 32;   // warp row origin (2 warps in m)
    const int wn = (warp & 3) * 32;    // warp col origin (4 warps in n)
    const int bm = blockIdx.y * BM1;
    const int bn = blockIdx.x * BN1;

    // A staging: one float4 per thread
    const int ar = tid >> 2;           // 0..63
    const int ac = (tid & 3) << 2;     // 0,4,8,12

    float acc[2][4][4];
#pragma unroll
    for (int i = 0; i < 2; i++)
#pragma unroll
        for (int j = 0; j < 4; j++)
#pragma unroll
            for (int r = 0; r < 4; r++) acc[i][j][r] = 0.f;

    auto loadA = [&](int kt, float4& v) {
        const size_t off = (size_t)(bm + ar) * DD + kt * BKK + ac;
        float4 y4 = *(const float4*)(g_ycur + off);
        float4 k4 = *(const float4*)(g_kbuf + off);
        v.x = fmaf(cf, k4.x, y4.x);
        v.y = fmaf(cf, k4.y, y4.y);
        v.z = fmaf(cf, k4.z, y4.z);
        v.w = fmaf(cf, k4.w, y4.w);
    };
    auto loadB = [&](int kt, float4 v[2]) {
#pragma unroll
        for (int l = 0; l < 2; l++) {
            int idx = tid + l * 256;
            int br = idx >> 5, bc = (idx & 31) << 2;
            v[l] = *(const float4*)(W1 + (size_t)(kt * BKK + br) * HH + bn + bc);
        }
    };
    auto stA = [&](int buf, const float4& v) {
        uint32_t* p = &sA[buf][ar * LDA + ac];
        p[0] = f2tf(v.x); p[1] = f2tf(v.y); p[2] = f2tf(v.z); p[3] = f2tf(v.w);
    };
    auto stB = [&](int buf, const float4 v[2]) {
#pragma unroll
        for (int l = 0; l < 2; l++) {
            int idx = tid + l * 256;
            int br = idx >> 5, bc = (idx & 31) << 2;
            uint32_t* p = &sB[buf][br * LDB1 + bc];
            p[0] = f2tf(v[l].x); p[1] = f2tf(v[l].y); p[2] = f2tf(v[l].z); p[3] = f2tf(v[l].w);
        }
    };
    auto compute = [&](int buf) {
#pragma unroll
        for (int ks = 0; ks < BKK; ks += 8) {
            uint32_t af[2][4], bf[4][2];
#pragma unroll
            for (int i = 0; i < 2; i++) {
                const uint32_t* base = &sA[buf][(wm + i * 16 + g) * LDA + ks + tg];
                af[i][0] = base[0];
                af[i][1] = base[8 * LDA];
                af[i][2] = base[4];
                af[i][3] = base[8 * LDA + 4];
            }
#pragma unroll
            for (int j = 0; j < 4; j++) {
                const uint32_t* base = &sB[buf][(ks + tg) * LDB1 + wn + j * 8 + g];
                bf[j][0] = base[0];
                bf[j][1] = base[4 * LDB1];
            }
#pragma unroll
            for (int i = 0; i < 2; i++)
#pragma unroll
                for (int j = 0; j < 4; j++)
                    mma_tf32(acc[i][j], af[i][0], af[i][1], af[i][2], af[i][3],
                             bf[j][0], bf[j][1]);
        }
    };

    const int NT = DD / BKK;  // 32
    float4 va; float4 vb[2];
    loadA(0, va); loadB(0, vb);
    stA(0, va); stB(0, vb);
    __syncthreads();
    int cur = 0;
    for (int kt = 0; kt < NT; kt++) {
        if (kt + 1 < NT) { loadA(kt + 1, va); loadB(kt + 1, vb); }
        compute(cur);
        if (kt + 1 < NT) {
            stA(cur ^ 1, va); stB(cur ^ 1, vb);
            __syncthreads();
            cur ^= 1;
        }
    }

    // epilogue: tanh(acc + b1)
#pragma unroll
    for (int i = 0; i < 2; i++)
#pragma unroll
        for (int j = 0; j < 4; j++)
#pragma unroll
            for (int r = 0; r < 4; r++) {
                int row = bm + wm + i * 16 + g + ((r >= 2) ? 8 : 0);
                int col = bn + wn + j * 8 + tg * 2 + (r & 1);
                g_h[(size_t)row * HH + col] = tanhf(acc[i][j][r] + b1[col]);
            }
}

// ============================================================================
// GEMM2: C = g_h [BB x HH] @ W2 [HH x DD]; epilogue does RK4 bookkeeping.
// CTA tile 64x64, BK=16, 256 threads, warps 2x4, warp tile 32x16.
// ============================================================================
#define BM2 64
#define BN2 64
#define LDB2 72   // BN2 + 8 (72 % 32 == 8 -> conflict-free)

__global__ __launch_bounds__(256) void gemm2_kernel(const float* __restrict__ W2,
                                                    const float* __restrict__ b2,
                                                    const float* __restrict__ tarr,
                                                    float* __restrict__ out,
                                                    int s, float w, int first, int last) {
    __shared__ uint32_t sA[2][BM2 * LDA];
    __shared__ uint32_t sB[2][BKK * LDB2];

    const int tid = threadIdx.x;
    const int lane = tid & 31, warp = tid >> 5;
    const int g = lane >> 2, tg = lane & 3;
    const int wm = (warp >> 2) * 32;
    const int wn = (warp & 3) * 16;
    const int bm = blockIdx.y * BM2;
    const int bn = blockIdx.x * BN2;

    const int ar = tid >> 2;          // 0..63
    const int ac = (tid & 3) << 2;    // 0,4,8,12
    const int br = tid >> 4;          // 0..15
    const int bc = (tid & 15) << 2;   // 0..60

    float acc[2][2][4];
#pragma unroll
    for (int i = 0; i < 2; i++)
#pragma unroll
        for (int j = 0; j < 2; j++)
#pragma unroll
            for (int r = 0; r < 4; r++) acc[i][j][r] = 0.f;

    auto loadA = [&](int kt, float4& v) {
        v = *(const float4*)(g_h + (size_t)(bm + ar) * HH + kt * BKK + ac);
    };
    auto loadB = [&](int kt, float4& v) {
        v = *(const float4*)(W2 + (size_t)(kt * BKK + br) * DD + bn + bc);
    };
    auto stA = [&](int buf, const float4& v) {
        uint32_t* p = &sA[buf][ar * LDA + ac];
        p[0] = f2tf(v.x); p[1] = f2tf(v.y); p[2] = f2tf(v.z); p[3] = f2tf(v.w);
    };
    auto stB = [&](int buf, const float4& v) {
        uint32_t* p = &sB[buf][br * LDB2 + bc];
        p[0] = f2tf(v.x); p[1] = f2tf(v.y); p[2] = f2tf(v.z); p[3] = f2tf(v.w);
    };
    auto compute = [&](int buf) {
#pragma unroll
        for (int ks = 0; ks < BKK; ks += 8) {
            uint32_t af[2][4], bf[2][2];
#pragma unroll
            for (int i = 0; i < 2; i++) {
                const uint32_t* base = &sA[buf][(wm + i * 16 + g) * LDA + ks + tg];
                af[i][0] = base[0];
                af[i][1] = base[8 * LDA];
                af[i][2] = base[4];
                af[i][3] = base[8 * LDA + 4];
            }
#pragma unroll
            for (int j = 0; j < 2; j++) {
                const uint32_t* base = &sB[buf][(ks + tg) * LDB2 + wn + j * 8 + g];
                bf[j][0] = base[0];
                bf[j][1] = base[4 * LDB2];
            }
#pragma unroll
            for (int i = 0; i < 2; i++)
#pragma unroll
                for (int j = 0; j < 2; j++)
                    mma_tf32(acc[i][j], af[i][0], af[i][1], af[i][2], af[i][3],
                             bf[j][0], bf[j][1]);
        }
    };

    const int NT = HH / BKK;  // 128
    float4 va, vb;
    loadA(0, va); loadB(0, vb);
    stA(0, va); stB(0, vb);
    __syncthreads();
    int cur = 0;
    for (int kt = 0; kt < NT; kt++) {
        if (kt + 1 < NT) { loadA(kt + 1, va); loadB(kt + 1, vb); }
        compute(cur);
        if (kt + 1 < NT) {
            stA(cur ^ 1, va); stB(cur ^ 1, vb);
            __syncthreads();
            cur ^= 1;
        }
    }

    // epilogue: k_new = dt * (acc + b2); RK4 accumulation; final combine/output
    const float inv6 = 1.0f / 6.0f;
#pragma unroll
    for (int i = 0; i < 2; i++)
#pragma unroll
        for (int j = 0; j < 2; j++)
#pragma unroll
            for (int r = 0; r < 4; r++) {
                int row = bm + wm + i * 16 + g + ((r >= 2) ? 8 : 0);
                int col = bn + wn + j * 8 + tg * 2 + (r & 1);
                float dt = tarr[(size_t)(s + 1) * BB + row] - tarr[(size_t)s * BB + row];
                float knew = dt * (acc[i][j][r] + b2[col]);
                size_t off = (size_t)row * DD + col;
                g_kbuf[off] = knew;
                float a = first ? (w * knew) : (g_acc[off] + w * knew);
                if (!last) {
                    g_acc[off] = a;
                } else {
                    float yn = g_ycur[off] + a * inv6;
                    g_ycur[off] = yn;
                    out[(size_t)(s + 1) * BB * DD + off] = yn;
                }
            }
}

// ---------------------------------------------------------------------------
extern "C" void kernel_launch(void* const* d_in, const int* in_sizes, int n_in,
                              void* d_out, int out_size) {
    const float* y0 = (const float*)d_in[0];
    const float* t  = (const float*)d_in[1];
    const float* W1 = (const float*)d_in[2];
    const float* b1 = (const float*)d_in[3];
    const float* W2 = (const float*)d_in[4];
    const float* b2 = (const float*)d_in[5];
    float* out = (float*)d_out;

    // out[0] = y0; g_ycur = y0
    init_kernel<<<(BB * DD / 4) / 256, 256>>>(y0, out);

    const float cs[4] = {0.0f, 0.5f, 0.5f, 1.0f};
    const float ws[4] = {1.0f, 2.0f, 2.0f, 1.0f};

    dim3 grid1(HH / BN1, BB / BM1);  // 16 x 8 = 128 CTAs
    dim3 grid2(DD / BN2, BB / BM2);  // 8 x 8  = 64 CTAs

    for (int s = 0; s < TT - 1; ++s) {
        for (int i = 0; i < 4; ++i) {
            gemm1_kernel<<<grid1, 256>>>(W1, b1, cs[i]);
            gemm2_kernel<<<grid2, 256>>>(W2, b2, t, out, s, ws[i],
                                         (i == 0) ? 1 : 0, (i == 3) ? 1 : 0);
        }
    }
}

// round 2
// speedup vs baseline: 3.2903x; 3.2903x over previous
#include <cuda_runtime.h>
#include <cuda_fp16.h>
#include <cstdint>
#include <cstddef>

#define TT 64
#define BB 512
#define DD 512
#define HH 2048

// ---------------- scratch (device globals) ---------------------------------
__device__ __align__(16) float  g_ycur[BB * DD];         // current state y (fp32)
__device__ __align__(16) float  g_acc [BB * DD];         // RK accumulator
__device__ __align__(16) __half g_a   [BB * DD];         // A operand of gemm1: y + c*k (half)
__device__ __align__(16) __half g_h   [(size_t)BB * HH]; // tanh hidden (half)
__device__ __align__(16) __half g_W1h [(size_t)DD * HH];
__device__ __align__(16) __half g_W2h [(size_t)HH * DD];

// ---------------- ptx helpers ----------------------------------------------
__device__ __forceinline__ uint32_t su32(const void* p) {
    return (uint32_t)__cvta_generic_to_shared(p);
}
#define CPA16(dst, src) \
    asm volatile("cp.async.cg.shared.global [%0], [%1], 16;" :: "r"(dst), "l"(src))
#define CP_COMMIT() asm volatile("cp.async.commit_group;")
#define CP_WAIT1()  asm volatile("cp.async.wait_group 1;")

__device__ __forceinline__ void ldsm_x4(uint32_t a[4], uint32_t addr) {
    asm volatile("ldmatrix.sync.aligned.m8n8.x4.shared.b16 {%0,%1,%2,%3}, [%4];"
                 : "=r"(a[0]), "=r"(a[1]), "=r"(a[2]), "=r"(a[3]) : "r"(addr));
}
__device__ __forceinline__ void ldsm_x4_t(uint32_t a[4], uint32_t addr) {
    asm volatile("ldmatrix.sync.aligned.m8n8.x4.trans.shared.b16 {%0,%1,%2,%3}, [%4];"
                 : "=r"(a[0]), "=r"(a[1]), "=r"(a[2]), "=r"(a[3]) : "r"(addr));
}
__device__ __forceinline__ void mma_fp16(float c[4], const uint32_t a[4],
                                         uint32_t b0, uint32_t b1) {
    asm volatile(
        "mma.sync.aligned.m16n8k16.row.col.f32.f16.f16.f32 "
        "{%0,%1,%2,%3},{%4,%5,%6,%7},{%8,%9},{%0,%1,%2,%3};"
        : "+f"(c[0]), "+f"(c[1]), "+f"(c[2]), "+f"(c[3])
        : "r"(a[0]), "r"(a[1]), "r"(a[2]), "r"(a[3]), "r"(b0), "r"(b1));
}

// ---------------- init / convert -------------------------------------------
__global__ void init_state(const float* __restrict__ y0, float* __restrict__ out) {
    int idx = blockIdx.x * blockDim.x + threadIdx.x;  // float4 index
    float4 v = ((const float4*)y0)[idx];
    ((float4*)out)[idx] = v;
    ((float4*)g_ycur)[idx] = v;
    __half2* a2 = (__half2*)g_a;
    a2[idx * 2]     = __floats2half2_rn(v.x, v.y);
    a2[idx * 2 + 1] = __floats2half2_rn(v.z, v.w);
}
__global__ void convert_w(const float* __restrict__ src, __half* __restrict__ dst) {
    int idx = blockIdx.x * blockDim.x + threadIdx.x;  // float4 index
    float4 v = ((const float4*)src)[idx];
    __half2* d2 = (__half2*)dst;
    d2[idx * 2]     = __floats2half2_rn(v.x, v.y);
    d2[idx * 2 + 1] = __floats2half2_rn(v.z, v.w);
}

// ============================================================================
// GEMM1: g_h = tanh( g_a[BBxDD] @ W1h[DDxHH] + b1 ), half in, half out
// CTA 64x128, BK=32, 3-stage cp.async, 256 thr, warps 2x4, warp tile 32x32
// smem pitches: A 40 halves (80B -> 20-bank stride, conflict-free ldmatrix),
//               B 136 halves (272B -> +4-bank stride, conflict-free)
// ============================================================================
#define G1_LA 40
#define G1_LB 136

__global__ __launch_bounds__(256) void gemm1_kernel(const float* __restrict__ b1) {
    __shared__ __half sA[3][64 * G1_LA];
    __shared__ __half sB[3][32 * G1_LB];

    const int tid = threadIdx.x, lane = tid & 31, warp = tid >> 5;
    const int g = lane >> 2, tg = lane & 3;
    const int wm = (warp >> 2) * 32, wn = (warp & 3) * 32;
    const int bm = blockIdx.y * 64, bn = blockIdx.x * 128;

    const int ar = tid >> 2, ac = (tid & 3) * 8;   // A: 256 chunks (64 rows x 4)
    const int br = tid >> 4, bc = (tid & 15) * 8;  // B: 512 chunks (32 rows x 16), 2/thread

    const int a_r = lane & 15, a_g = (lane >> 4) * 8;   // ldmatrix lane offsets
    const int b_k = lane & 15, b_g = (lane >> 4) * 8;

    float acc[2][4][4];
#pragma unroll
    for (int i = 0; i < 2; i++)
#pragma unroll
        for (int j = 0; j < 4; j++)
#pragma unroll
            for (int r = 0; r < 4; r++) acc[i][j][r] = 0.f;

    auto loadTile = [&](int st, int kt) {
        CPA16(su32(&sA[st][ar * G1_LA + ac]),
              g_a + (size_t)(bm + ar) * DD + kt * 32 + ac);
        CPA16(su32(&sB[st][br * G1_LB + bc]),
              g_W1h + (size_t)(kt * 32 + br) * HH + bn + bc);
        CPA16(su32(&sB[st][(br + 16) * G1_LB + bc]),
              g_W1h + (size_t)(kt * 32 + br + 16) * HH + bn + bc);
    };

    const int NT = DD / 32;  // 16
    loadTile(0, 0); CP_COMMIT();
    loadTile(1, 1); CP_COMMIT();

    int st = 0;
    for (int kt = 0; kt < NT; kt++) {
        CP_WAIT1();
        __syncthreads();
        if (kt + 2 < NT) loadTile((st + 2) % 3, kt + 2);
        CP_COMMIT();
#pragma unroll
        for (int ks = 0; ks < 32; ks += 16) {
            uint32_t A[2][4], Bf[4][2];
#pragma unroll
            for (int mt = 0; mt < 2; mt++)
                ldsm_x4(A[mt], su32(&sA[st][(wm + mt * 16 + a_r) * G1_LA + ks + a_g]));
#pragma unroll
            for (int bt = 0; bt < 2; bt++) {
                uint32_t r[4];
                ldsm_x4_t(r, su32(&sB[st][(ks + b_k) * G1_LB + wn + bt * 16 + b_g]));
                Bf[bt * 2][0] = r[0]; Bf[bt * 2][1] = r[1];
                Bf[bt * 2 + 1][0] = r[2]; Bf[bt * 2 + 1][1] = r[3];
            }
#pragma unroll
            for (int mt = 0; mt < 2; mt++)
#pragma unroll
                for (int nt = 0; nt < 4; nt++)
                    mma_fp16(acc[mt][nt], A[mt], Bf[nt][0], Bf[nt][1]);
        }
        st = (st + 1) % 3;
        __syncthreads();
    }

    // epilogue: tanh(acc + b1) -> half2 stores
#pragma unroll
    for (int mt = 0; mt < 2; mt++)
#pragma unroll
        for (int nt = 0; nt < 4; nt++) {
            int col = bn + wn + nt * 8 + tg * 2;
            float bc0 = b1[col], bc1 = b1[col + 1];
#pragma unroll
            for (int half_r = 0; half_r < 2; half_r++) {
                int row = bm + wm + mt * 16 + g + half_r * 8;
                float v0 = tanhf(acc[mt][nt][half_r * 2 + 0] + bc0);
                float v1 = tanhf(acc[mt][nt][half_r * 2 + 1] + bc1);
                *(__half2*)&g_h[(size_t)row * HH + col] = __floats2half2_rn(v0, v1);
            }
        }
}

// ============================================================================
// GEMM2: C = g_h[BBxHH] @ W2h[HHxDD]; epilogue = RK4 bookkeeping + next A op
// CTA 32x64 (grid 8x16 = 128 CTAs), BK=32, 3-stage, 256 thr, warps 2x4,
// warp tile 16x16
// ============================================================================
#define G2_LA 40
#define G2_LB 72

__global__ __launch_bounds__(256) void gemm2_kernel(const float* __restrict__ b2,
                                                    const float* __restrict__ tarr,
                                                    float* __restrict__ out,
                                                    int s, float w, float cnext,
                                                    int first, int last) {
    __shared__ __half sA[3][32 * G2_LA];
    __shared__ __half sB[3][32 * G2_LB];

    const int tid = threadIdx.x, lane = tid & 31, warp = tid >> 5;
    const int g = lane >> 2, tg = lane & 3;
    const int wm = (warp >> 2) * 16, wn = (warp & 3) * 16;
    const int bm = blockIdx.y * 32, bn = blockIdx.x * 64;

    const int ar = tid >> 2, ac = (tid & 3) * 8;   // A: 128 chunks (tid<128)
    const int br = tid >> 3, bc = (tid & 7) * 8;   // B: 256 chunks

    const int a_r = lane & 15, a_g = (lane >> 4) * 8;
    const int b_k = lane & 15, b_g = (lane >> 4) * 8;

    float acc[2][4];
#pragma unroll
    for (int j = 0; j < 2; j++)
#pragma unroll
        for (int r = 0; r < 4; r++) acc[j][r] = 0.f;

    auto loadTile = [&](int st, int kt) {
        if (tid < 128)
            CPA16(su32(&sA[st][ar * G2_LA + ac]),
                  g_h + (size_t)(bm + ar) * HH + kt * 32 + ac);
        CPA16(su32(&sB[st][br * G2_LB + bc]),
              g_W2h + (size_t)(kt * 32 + br) * DD + bn + bc);
    };

    const int NT = HH / 32;  // 64
    loadTile(0, 0); CP_COMMIT();
    loadTile(1, 1); CP_COMMIT();

    int st = 0;
    for (int kt = 0; kt < NT; kt++) {
        CP_WAIT1();
        __syncthreads();
        if (kt + 2 < NT) loadTile((st + 2) % 3, kt + 2);
        CP_COMMIT();
#pragma unroll
        for (int ks = 0; ks < 32; ks += 16) {
            uint32_t A[4], Bf[4];
            ldsm_x4(A, su32(&sA[st][(wm + a_r) * G2_LA + ks + a_g]));
            ldsm_x4_t(Bf, su32(&sB[st][(ks + b_k) * G2_LB + wn + b_g]));
            mma_fp16(acc[0], A, Bf[0], Bf[1]);
            mma_fp16(acc[1], A, Bf[2], Bf[3]);
        }
        st = (st + 1) % 3;
        __syncthreads();
    }

    // epilogue: knew = dt*(acc+b2); RK accumulation; produce next A operand
    const float inv6 = 1.0f / 6.0f;
#pragma unroll
    for (int nt = 0; nt < 2; nt++)
#pragma unroll
        for (int r = 0; r < 4; r++) {
            int row = bm + wm + g + ((r >= 2) ? 8 : 0);
            int col = bn + wn + nt * 8 + tg * 2 + (r & 1);
            float dt = tarr[(size_t)(s + 1) * BB + row] - tarr[(size_t)s * BB + row];
            float knew = dt * (acc[nt][r] + b2[col]);
            size_t off = (size_t)row * DD + col;
            float a = first ? (w * knew) : (g_acc[off] + w * knew);
            if (!last) {
                g_acc[off] = a;
                g_a[off] = __float2half(g_ycur[off] + cnext * knew);
            } else {
                float yn = g_ycur[off] + a * inv6;
                g_ycur[off] = yn;
                out[(size_t)(s + 1) * BB * DD + off] = yn;
                g_a[off] = __float2half(yn);
            }
        }
}

// ---------------------------------------------------------------------------
extern "C" void kernel_launch(void* const* d_in, const int* in_sizes, int n_in,
                              void* d_out, int out_size) {
    const float* y0 = (const float*)d_in[0];
    const float* t  = (const float*)d_in[1];
    const float* W1 = (const float*)d_in[2];
    const float* b1 = (const float*)d_in[3];
    const float* W2 = (const float*)d_in[4];
    const float* b2 = (const float*)d_in[5];
    float* out = (float*)d_out;

    __half* w1h; cudaGetSymbolAddress((void**)&w1h, g_W1h);
    __half* w2h; cudaGetSymbolAddress((void**)&w2h, g_W2h);

    init_state<<<(BB * DD / 4) / 256, 256>>>(y0, out);
    convert_w<<<(DD * HH / 4) / 256, 256>>>(W1, w1h);
    convert_w<<<(HH * DD / 4) / 256, 256>>>(W2, w2h);

    const float ws[4] = {1.0f, 2.0f, 2.0f, 1.0f};
    const float cn[4] = {0.5f, 0.5f, 1.0f, 0.0f};

    dim3 grid1(HH / 128, BB / 64);  // 16 x 8  = 128 CTAs
    dim3 grid2(DD / 64,  BB / 32);  // 8  x 16 = 128 CTAs

    for (int s = 0; s < TT - 1; ++s) {
        for (int i = 0; i < 4; ++i) {
            gemm1_kernel<<<grid1, 256>>>(b1);
            gemm2_kernel<<<grid2, 256>>>(b2, t, out, s, ws[i], cn[i],
                                         (i == 0) ? 1 : 0, (i == 3) ? 1 : 0);
        }
    }
}